// round 3
// baseline (speedup 1.0000x reference)
#include <cuda_runtime.h>
#include <cuda_bf16.h>

// Problem constants (fixed shapes for MultiBoxLoss300)
#define NPRIORS   22536
#define NBATCH    32
#define NOBJ      16
#define NCLS      81
#define NTOTAL    (NBATCH * NPRIORS)      // 721152

#define FUSED_BLOCKS 592                  // 4 blocks/SM x 148 SMs, single wave
#define FUSED_TPB    256
#define FUSED_WARPS  (FUSED_BLOCKS * (FUSED_TPB / 32))   // 4736
#define CHUNK        ((NTOTAL + FUSED_WARPS - 1) / FUSED_WARPS)  // 153

typedef unsigned long long u64;

// Scratch (device globals; no dynamic allocation allowed)
__device__ u64    g_scr[NTOTAL];          // per-(b,prior): hi32 = float bits of ov, lo32 = obj idx
__device__ u64    g_best[NBATCH * NOBJ];  // per-(b,obj): hi32 = iou bits, lo32 = 0xFFFFFFFF - prior
__device__ double g_acc[4];               // conf_sum, n_include, loc_sum, n_pos

// ---------------------------------------------------------------------------
// Kernel 0: init accumulators + per-object argmax slots
// ---------------------------------------------------------------------------
__global__ void init_kernel() {
    int i = threadIdx.x;
    if (i < NBATCH * NOBJ) g_best[i] = 0xFFFFFFFFULL;   // pack(0.0f, prior 0)
    if (i < 4) g_acc[i] = 0.0;
}

// ---------------------------------------------------------------------------
// Kernel 1: matching. Per (b, prior): IoU against 16 boxes.
//   - row max (over objects, first-index ties)  -> g_scr
//   - column max (over priors, first-index ties) -> g_best via packed atomicMax
// fp32 op order mirrors the JAX reference (IEEE div; only exact-product
// contractions) so threshold/argmax decisions cannot flip.
// Column argmax per warp: redux.max on float bits (iou >= 0 so uint order ==
// float order) + ballot + ffs (lowest lane = lowest prior = first index).
// ---------------------------------------------------------------------------
__global__ __launch_bounds__(256) void match_kernel(const float* __restrict__ boxes,
                                                    const float* __restrict__ priors) {
    __shared__ float4 sbox[NOBJ];
    __shared__ float  sba[NOBJ];
    __shared__ u64    smax[NOBJ];

    const unsigned FULL = 0xFFFFFFFFu;
    int b = blockIdx.y;
    int tid = threadIdx.x;
    int lane = tid & 31;
    int p = blockIdx.x * 256 + tid;
    int p0 = blockIdx.x * 256 + (tid & ~31);   // warp's first prior

    if (tid < NOBJ) {
        float4 tb = ((const float4*)boxes)[b * NOBJ + tid];
        sbox[tid] = tb;
        sba[tid] = (tb.z - tb.x) * (tb.w - tb.y);
        smax[tid] = 0ULL;
    }
    __syncthreads();

    bool valid = (p < NPRIORS);
    int pc = valid ? p : (NPRIORS - 1);
    float4 pr = ((const float4*)priors)[pc];
    float px1 = pr.x - pr.z * 0.5f;
    float py1 = pr.y - pr.w * 0.5f;
    float px2 = pr.x + pr.z * 0.5f;
    float py2 = pr.y + pr.w * 0.5f;
    float pa = (px2 - px1) * (py2 - py1);

    float bestv = -1.0f;
    int besto = 0;

    #pragma unroll
    for (int o = 0; o < NOBJ; o++) {
        float4 tb = sbox[o];
        float iw = fmaxf(fminf(px2, tb.z) - fmaxf(px1, tb.x), 0.0f);
        float ih = fmaxf(fminf(py2, tb.w) - fmaxf(py1, tb.y), 0.0f);
        float inter = iw * ih;
        float iou = inter / ((sba[o] + pa) - inter);   // IEEE division, matches XLA
        if (valid && iou > bestv) { bestv = iou; besto = o; }  // strict > keeps first index

        unsigned bits = valid ? __float_as_uint(iou) : 0u;
        unsigned mx = __reduce_max_sync(FULL, bits);
        unsigned msk = __ballot_sync(FULL, bits == mx);
        if (lane == 0) {
            int src = __ffs(msk) - 1;  // lowest lane -> lowest prior -> first index
            u64 pk = (((u64)mx) << 32) | (u64)(0xFFFFFFFFu - (unsigned)(p0 + src));
            atomicMax(&smax[o], pk);
        }
    }

    if (valid)
        g_scr[(size_t)b * NPRIORS + p] =
            (((u64)__float_as_uint(bestv)) << 32) | (unsigned)besto;

    __syncthreads();
    if (tid < NOBJ) atomicMax(&g_best[b * NOBJ + tid], smax[tid]);
}

// ---------------------------------------------------------------------------
// Kernel 2: fused focal + DIoU loss. WARP-PER-PRIOR: lanes cooperatively read
// one 81-class row (3 coalesced LDGs), butterfly-reduce the exp sum, fetch
// s[t] with one shfl. No shared-memory tile, no syncthreads in the hot loop
// -> ~32 warps/SM residency. Override (g_best) folded in via ballot so the
// separate override kernel is gone.
// ---------------------------------------------------------------------------
__global__ __launch_bounds__(FUSED_TPB, 4) void fused_loss_kernel(
    const float* __restrict__ scores,
    const float* __restrict__ locs,
    const float* __restrict__ boxes,
    const int*   __restrict__ labels,
    const float* __restrict__ priors) {

    const unsigned FULL = 0xFFFFFFFFu;
    int lane = threadIdx.x & 31;
    int wid = threadIdx.x >> 5;
    int gw = blockIdx.x * (FUSED_TPB / 32) + wid;

    int f = gw * CHUNK;
    int end = f + CHUNK;
    if (end > NTOTAL) end = NTOTAL;

    // warp-uniform accumulators (every lane holds the same value)
    float conf_acc = 0.f, loc_acc = 0.f;
    unsigned inc_cnt = 0, pos_cnt = 0;

    if (f < end) {
        int b = f / NPRIORS;
        int bBase = b * NPRIORS;
        int bnd = bBase + NPRIORS;

        // per-batch cached state on lanes 0..15: override prior + label
        unsigned obest_p = 0xFFFFFFFFu;
        int olab = 0;
        if (lane < NOBJ) {
            u64 q = g_best[b * NOBJ + lane];
            obest_p = 0xFFFFFFFFu - (unsigned)(q & 0xFFFFFFFFu);
            olab = labels[b * NOBJ + lane];
        }

        auto process = [&](int ff, float v0, float v1, float v2, u64 pk) {
            // sum of exp over 81 classes (lanes >= 17 hold -1e30 -> exp == 0)
            float e = __expf(v0) + __expf(v1) + __expf(v2);
            #pragma unroll
            for (int off = 16; off; off >>= 1)
                e += __shfl_xor_sync(FULL, e, off);

            int p = ff - bBase;
            // override check: does any object's best prior equal p?
            unsigned m = __ballot_sync(FULL, (lane < NOBJ) && (obest_p == (unsigned)p));

            float ov = __uint_as_float((unsigned)(pk >> 32));
            int obj = (int)(unsigned)(pk & 0xFFFFFFFFu);
            int obj_eff = m ? (31 - __clz(m)) : obj;   // highest o = last-wins
            int lab = __shfl_sync(FULL, olab, obj_eff);
            if (!m) {
                if (ov < 0.5f) lab = -1;
                if (ov < 0.4f) lab = 0;
            }

            int t = lab > 0 ? lab : 0;
            int sl = t & 31;
            float s0 = __shfl_sync(FULL, v0, sl);
            float s1 = __shfl_sync(FULL, v1, sl);
            float s2 = __shfl_sync(FULL, v2, sl);
            float st = t < 32 ? s0 : (t < 64 ? s1 : s2);

            float lse = __logf(e);
            float logpt = st - lse;
            float pt = __expf(logpt);
            float om = 1.0f - pt;
            float focal = -(om * om) * logpt;

            if (lab >= 0) { conf_acc += focal; inc_cnt++; }
            if (lab > 0) {           // warp-uniform, rare
                pos_cnt++;
                float4 g  = ((const float4*)locs)[ff];          // broadcast
                float4 pr = ((const float4*)priors)[p];
                float4 tb = ((const float4*)boxes)[b * NOBJ + obj_eff];
                float cx = g.x * pr.z / 10.0f + pr.x;
                float cy = g.y * pr.w / 10.0f + pr.y;
                float w  = __expf(g.z / 5.0f) * pr.z;
                float h  = __expf(g.w / 5.0f) * pr.w;
                float px1 = cx - w * 0.5f, py1 = cy - h * 0.5f;
                float px2 = cx + w * 0.5f, py2 = cy + h * 0.5f;
                float iw = fmaxf(fminf(px2, tb.z) - fmaxf(px1, tb.x), 0.0f);
                float ih = fmaxf(fminf(py2, tb.w) - fmaxf(py1, tb.y), 0.0f);
                float inter = iw * ih;
                float ap = (px2 - px1) * (py2 - py1);
                float at = (tb.z - tb.x) * (tb.w - tb.y);
                float iou = inter / ((ap + at) - inter);
                float cpx = (px1 + px2) * 0.5f, cpy = (py1 + py2) * 0.5f;
                float ctx = (tb.x + tb.z) * 0.5f, cty = (tb.y + tb.w) * 0.5f;
                float dx = cpx - ctx, dy = cpy - cty;
                float interd = dx * dx + dy * dy;
                float ox1 = fminf(px1, tb.x), oy1 = fminf(py1, tb.y);
                float ox2 = fmaxf(px2, tb.z), oy2 = fmaxf(py2, tb.w);
                float ow = fmaxf(ox2 - ox1, 0.0f), oh = fmaxf(oy2 - oy1, 0.0f);
                float outerd = ow * ow + oh * oh;
                float d = iou - interd / outerd;
                d = fminf(fmaxf(d, -1.0f), 1.0f);
                loc_acc += 1.0f - d;
            }
        };

        while (f < end) {
            int lim = end < bnd ? end : bnd;
            // 2-way unrolled pairs: all loads issued up front for MLP
            for (; f + 1 < lim; f += 2) {
                const float* rowA = scores + (size_t)f * NCLS;
                const float* rowB = rowA + NCLS;
                float a0 = rowA[lane];
                float a1 = rowA[32 + lane];
                float a2 = (lane < 17) ? rowA[64 + lane] : -1e30f;
                float b0 = rowB[lane];
                float b1 = rowB[32 + lane];
                float b2 = (lane < 17) ? rowB[64 + lane] : -1e30f;
                u64 pkA = g_scr[f];
                u64 pkB = g_scr[f + 1];
                process(f, a0, a1, a2, pkA);
                process(f + 1, b0, b1, b2, pkB);
            }
            for (; f < lim; f++) {
                const float* row = scores + (size_t)f * NCLS;
                float a0 = row[lane];
                float a1 = row[32 + lane];
                float a2 = (lane < 17) ? row[64 + lane] : -1e30f;
                u64 pkA = g_scr[f];
                process(f, a0, a1, a2, pkA);
            }
            if (f < end) {   // crossed batch boundary
                b++; bBase = bnd; bnd += NPRIORS;
                if (lane < NOBJ) {
                    u64 q = g_best[b * NOBJ + lane];
                    obest_p = 0xFFFFFFFFu - (unsigned)(q & 0xFFFFFFFFu);
                    olab = labels[b * NOBJ + lane];
                }
            }
        }
    }

    // block reduce (accumulators are warp-uniform: lane 0 value is the warp sum)
    __shared__ float sc[FUSED_TPB / 32], sl_[FUSED_TPB / 32];
    __shared__ unsigned si[FUSED_TPB / 32], sp[FUSED_TPB / 32];
    if (lane == 0) { sc[wid] = conf_acc; sl_[wid] = loc_acc; si[wid] = inc_cnt; sp[wid] = pos_cnt; }
    __syncthreads();
    if (threadIdx.x == 0) {
        float c = 0.f, l = 0.f; unsigned ki = 0, kp = 0;
        #pragma unroll
        for (int i = 0; i < FUSED_TPB / 32; i++) { c += sc[i]; l += sl_[i]; ki += si[i]; kp += sp[i]; }
        atomicAdd(&g_acc[0], (double)c);
        atomicAdd(&g_acc[1], (double)ki);
        atomicAdd(&g_acc[2], (double)l);
        atomicAdd(&g_acc[3], (double)kp);
    }
}

// ---------------------------------------------------------------------------
// Kernel 3: finalize
// ---------------------------------------------------------------------------
__global__ void finalize_kernel(float* out) {
    double npos = g_acc[3];
    double conf = g_acc[0] / g_acc[1] / npos;
    double loc = g_acc[2] / npos;
    out[0] = (float)(conf + 25.0 * loc);
}

// ---------------------------------------------------------------------------
// Launch. Inputs mapped defensively by element count (all five distinct).
// ---------------------------------------------------------------------------
extern "C" void kernel_launch(void* const* d_in, const int* in_sizes, int n_in,
                              void* d_out, int out_size) {
    const float* locs   = 0;
    const float* scores = 0;
    const float* boxes  = 0;
    const int*   labels = 0;
    const float* priors = 0;

    for (int i = 0; i < n_in; i++) {
        switch (in_sizes[i]) {
            case NTOTAL * 4:        locs   = (const float*)d_in[i]; break; // 2,884,608
            case NTOTAL * NCLS:     scores = (const float*)d_in[i]; break; // 58,413,312
            case NBATCH * NOBJ * 4: boxes  = (const float*)d_in[i]; break; // 2,048
            case NBATCH * NOBJ:     labels = (const int*)d_in[i];   break; // 512
            case NPRIORS * 4:       priors = (const float*)d_in[i]; break; // 90,144
        }
    }

    init_kernel<<<1, 512>>>();
    dim3 gA((NPRIORS + 255) / 256, NBATCH);
    match_kernel<<<gA, 256>>>(boxes, priors);
    fused_loss_kernel<<<FUSED_BLOCKS, FUSED_TPB>>>(scores, locs, boxes, labels, priors);
    finalize_kernel<<<1, 1>>>((float*)d_out);
}